// round 9
// baseline (speedup 1.0000x reference)
#include <cuda_runtime.h>
#include <cuda.h>
#include <cuda_fp16.h>
#include <cstdint>
#include <cstddef>

#define NN 4096
#define HH 64
#define EE 10
#define NC 192   // 3*H

// gemm1: persistent, BM=128, BK=64, 4-stage TMA pipeline, work-stealing over 320 items
#define G1_NSTAGE 4
#define G1_STAGE 25600            // A: 2*8192 (SW128 64x64 tiles) + B: 9216 (64 rows x 144B)
#define G1_SMEM (G1_NSTAGE * G1_STAGE + 1024)
#define G1_ITEMS 320              // 32 m-tiles x 10 edge types
#define G1_GRID 148
#define G1_NCONS 16               // consumer warps

// update: m-tile 32, triple-buffered e-pipeline
#define UP_ABYTES 4608            // 32 rows x 144B
#define UP_BBYTES 25600           // 64 rows x 400B
#define UP_BUF (UP_ABYTES + UP_BBYTES)   // 30208
#define UP_SMEM (3 * UP_BUF)             // 90624

// ---------------- scratch (device globals; no allocations allowed) ----------------
__device__ __half g_edge16[(size_t)EE * NN * NN];   // 335 MB, edge * 4096 in fp16, [e][k][m]
__device__ __half g_h16p[NN * 72];                  // hidden fp16, padded rows (144 B)
__device__ __half g_act16[(size_t)EE * NN * HH];    // per-edge aggregated messages
__device__ __half g_W16[EE * HH * NC];              // wz_wr_wh in fp16
__device__ __half g_uzurpad16[HH * NC];             // [uz|ur|0] padded to 192 cols
__device__ __half g_uh16[HH * HH];                  // uh in fp16
__device__ float  g_T0[NN * NC];                    // E * (input @ input_wzrh)
__device__ float  g_S[NN * NC];                     // gate pre-activations
__device__ int    g_ctr1[16];                       // per-iteration work-steal counters

// ---------------- PTX helpers ----------------
__device__ __forceinline__ void cp16(void* s, const void* g) {
    unsigned sa = (unsigned)__cvta_generic_to_shared(s);
    asm volatile("cp.async.cg.shared.global [%0], [%1], 16;" :: "r"(sa), "l"(g));
}
__device__ __forceinline__ void cp_commit() { asm volatile("cp.async.commit_group;"); }
template <int N_>
__device__ __forceinline__ void cp_wait() { asm volatile("cp.async.wait_group %0;" :: "n"(N_)); }

__device__ __forceinline__ void bulkcp(uint32_t dst, const void* src, uint32_t bytes, uint32_t mbar) {
    asm volatile("cp.async.bulk.shared::cta.global.mbarrier::complete_tx::bytes [%0], [%1], %2, [%3];"
                 :: "r"(dst), "l"(src), "r"(bytes), "r"(mbar) : "memory");
}
__device__ __forceinline__ void tma3d(uint32_t dst, const CUtensorMap* map,
                                      int x, int y, int z, uint32_t mbar) {
    asm volatile("cp.async.bulk.tensor.3d.shared::cta.global.tile.mbarrier::complete_tx::bytes "
                 "[%0], [%1, {%2, %3, %4}], [%5];"
                 :: "r"(dst), "l"(map), "r"(x), "r"(y), "r"(z), "r"(mbar) : "memory");
}
__device__ __forceinline__ void mbar_init(uint32_t mbar, uint32_t count) {
    asm volatile("mbarrier.init.shared.b64 [%0], %1;" :: "r"(mbar), "r"(count) : "memory");
}
__device__ __forceinline__ void mbar_expect_tx(uint32_t mbar, uint32_t bytes) {
    asm volatile("mbarrier.arrive.expect_tx.shared.b64 _, [%0], %1;" :: "r"(mbar), "r"(bytes) : "memory");
}
__device__ __forceinline__ void mbar_arrive(uint32_t mbar) {
    asm volatile("mbarrier.arrive.shared.b64 _, [%0];" :: "r"(mbar) : "memory");
}
__device__ __forceinline__ void mbar_wait_acq(uint32_t mbar, uint32_t parity) {
    asm volatile(
        "{\n\t.reg .pred P1;\n\t"
        "WAIT_LOOP_%=:\n\t"
        "mbarrier.try_wait.parity.acquire.cta.shared::cta.b64 P1, [%0], %1, 0x989680;\n\t"
        "@P1 bra.uni WAIT_DONE_%=;\n\t"
        "bra.uni WAIT_LOOP_%=;\n\t"
        "WAIT_DONE_%=:\n\t}"
        :: "r"(mbar), "r"(parity) : "memory");
}
__device__ __forceinline__ void mbar_wait_rlx(uint32_t mbar, uint32_t parity) {
    asm volatile(
        "{\n\t.reg .pred P1;\n\t"
        "WAIT_LOOP_%=:\n\t"
        "mbarrier.try_wait.parity.relaxed.cta.shared::cta.b64 P1, [%0], %1, 0x989680;\n\t"
        "@P1 bra.uni WAIT_DONE_%=;\n\t"
        "bra.uni WAIT_LOOP_%=;\n\t"
        "WAIT_DONE_%=:\n\t}"
        :: "r"(mbar), "r"(parity) : "memory");
}

// trans ldmatrix (operand stored [k][major])
__device__ __forceinline__ void ldsm4t(unsigned& r0, unsigned& r1, unsigned& r2, unsigned& r3,
                                       const void* p) {
    unsigned a = (unsigned)__cvta_generic_to_shared(p);
    asm volatile("ldmatrix.sync.aligned.m8n8.x4.trans.shared.b16 {%0,%1,%2,%3}, [%4];"
                 : "=r"(r0), "=r"(r1), "=r"(r2), "=r"(r3) : "r"(a));
}
__device__ __forceinline__ void ldsm4t_s(unsigned& r0, unsigned& r1, unsigned& r2, unsigned& r3,
                                         uint32_t a) {
    asm volatile("ldmatrix.sync.aligned.m8n8.x4.trans.shared.b16 {%0,%1,%2,%3}, [%4];"
                 : "=r"(r0), "=r"(r1), "=r"(r2), "=r"(r3) : "r"(a));
}
// non-trans ldmatrix (A stored row-major [m][k])
__device__ __forceinline__ void ldsm4(unsigned& r0, unsigned& r1, unsigned& r2, unsigned& r3,
                                      const void* p) {
    unsigned a = (unsigned)__cvta_generic_to_shared(p);
    asm volatile("ldmatrix.sync.aligned.m8n8.x4.shared.b16 {%0,%1,%2,%3}, [%4];"
                 : "=r"(r0), "=r"(r1), "=r"(r2), "=r"(r3) : "r"(a));
}
__device__ __forceinline__ void mma16816(float* c, const unsigned* a, const unsigned* b) {
    asm volatile(
        "mma.sync.aligned.m16n8k16.row.col.f32.f16.f16.f32 "
        "{%0,%1,%2,%3},{%4,%5,%6,%7},{%8,%9},{%0,%1,%2,%3};"
        : "+f"(c[0]), "+f"(c[1]), "+f"(c[2]), "+f"(c[3])
        : "r"(a[0]), "r"(a[1]), "r"(a[2]), "r"(a[3]), "r"(b[0]), "r"(b[1]));
}

__device__ __forceinline__ float sigm(float x) { return 1.0f / (1.0f + __expf(-x)); }
__device__ __forceinline__ float tanh_fast(float x) { return 2.0f / (1.0f + __expf(-2.0f * x)) - 1.0f; }

// ---------------- setup kernels ----------------
__global__ void k_conv_edge(const float* __restrict__ edge) {
    const size_t n8 = (size_t)EE * NN * NN / 8;
    const float4* src = (const float4*)edge;
    uint4* dst = (uint4*)g_edge16;
    for (size_t i = (size_t)blockIdx.x * blockDim.x + threadIdx.x; i < n8;
         i += (size_t)gridDim.x * blockDim.x) {
        float4 a = src[2 * i];
        float4 b = src[2 * i + 1];
        __half2 h0 = __floats2half2_rn(a.x * 4096.0f, a.y * 4096.0f);
        __half2 h1 = __floats2half2_rn(a.z * 4096.0f, a.w * 4096.0f);
        __half2 h2 = __floats2half2_rn(b.x * 4096.0f, b.y * 4096.0f);
        __half2 h3 = __floats2half2_rn(b.z * 4096.0f, b.w * 4096.0f);
        uint4 o;
        o.x = *(unsigned*)&h0; o.y = *(unsigned*)&h1;
        o.z = *(unsigned*)&h2; o.w = *(unsigned*)&h3;
        dst[i] = o;
    }
}

__global__ void k_setup(const float* __restrict__ hidden, const float* __restrict__ W,
                        const float* __restrict__ uzur, const float* __restrict__ uh,
                        float* __restrict__ dout) {
    int i = blockIdx.x * blockDim.x + threadIdx.x;   // grid covers 262144
    if (i < 16) g_ctr1[i] = 0;
    if (i < NN * HH) {
        float v = hidden[i]; dout[i] = v;
        g_h16p[(i >> 6) * 72 + (i & 63)] = __float2half_rn(v);
    }
    if (i < EE * HH * NC) g_W16[i] = __float2half_rn(W[i]);
    if (i < HH * NC) {
        int r = i / NC, c = i % NC;
        g_uzurpad16[i] = __float2half_rn(c < 2 * HH ? uzur[r * 2 * HH + c] : 0.0f);
    }
    if (i < HH * HH) g_uh16[i] = __float2half_rn(uh[i]);
}

__global__ void k_t0(const float* __restrict__ input, const float* __restrict__ iwzrh) {
    __shared__ float xs[HH];
    int row = blockIdx.x;
    int j = threadIdx.x;  // 0..191
    if (j < HH) xs[j] = input[row * HH + j];
    __syncthreads();
    float acc = 0.0f;
#pragma unroll 8
    for (int i = 0; i < HH; i++) acc += xs[i] * iwzrh[i * NC + j];
    g_T0[row * NC + j] = (float)EE * acc;
}

// ---------------- GEMM1 (persistent): act16[e] = edge[e]^T @ h + ba ----------------
// 148 CTAs, 16 consumer warps (each 16m x 32n) + 1 producer warp, work-steal 320 items.
__global__ __launch_bounds__(544, 1) void k_gemm1(const int* __restrict__ d_it, int it,
                                                  const float* __restrict__ ba,
                                                  const __grid_constant__ CUtensorMap tma_a) {
    if (it >= d_it[0]) return;
    extern __shared__ unsigned char dsm_raw[];
    __shared__ __align__(8) unsigned long long mbar_sto[2 * G1_NSTAGE];
    __shared__ int s_item;
    const uint32_t smem0 = ((uint32_t)__cvta_generic_to_shared(dsm_raw) + 1023u) & ~1023u;
    const uint32_t mb = (uint32_t)__cvta_generic_to_shared(mbar_sto);
    const int tid = threadIdx.x, w = tid >> 5, lane = tid & 31;

    if (tid == 0) {
        for (int s = 0; s < G1_NSTAGE; s++) {
            mbar_init(mb + s * 8, 1);                          // full: expect_tx arrival
            mbar_init(mb + (G1_NSTAGE + s) * 8, G1_NCONS);     // empty: 16 consumer warps
        }
    }

    // consumer fragment addressing (item-invariant)
    const int m_idx = w >> 1;            // 0..7, warp covers m [m_idx*16, +16)
    const int n_base = (w & 1) * 32;
    const int g = lane >> 3, r = lane & 7;
    const int a_k = ((g >> 1) & 1) * 8 + r;
    // A: two SW128 64x64 TMA tiles; warp's m within tile = (m_idx&3)*16
    const uint32_t a_qbase = (uint32_t)((m_idx >> 2) * 8192);
    const uint32_t aoff =
        (uint32_t)((a_k * 128 + ((m_idx & 3) * 16 + (g & 1) * 8) * 2) ^ (r << 4));
    const int b_k = (g & 1) * 8 + r;
    const int b_n = (g >> 1) * 8;
    const float inv = 1.0f / 4096.0f;
    __half2* actp = (__half2*)g_act16;

    // pipeline state persists across items
    int pst = 0, pph = 1;     // producer
    int cst = 0, cph = 0;     // consumer

    for (;;) {
        __syncthreads();
        if (tid == 0) s_item = atomicAdd(&g_ctr1[it], 1);
        __syncthreads();
        const int item = s_item;
        if (item >= G1_ITEMS) break;
        const int e = item / 32;
        const int m0 = (item & 31) * 128;

        if (w == 16) {
            if (lane == 0) {
                for (int kt = 0; kt < 64; kt++) {
                    const uint32_t fullb = mb + pst * 8;
                    const uint32_t emptyb = mb + (G1_NSTAGE + pst) * 8;
                    mbar_wait_rlx(emptyb, pph);
                    mbar_expect_tx(fullb, G1_STAGE);
                    const uint32_t sa = smem0 + pst * G1_STAGE;
                    tma3d(sa,        &tma_a, m0,      kt * 64, e, fullb);
                    tma3d(sa + 8192, &tma_a, m0 + 64, kt * 64, e, fullb);
                    bulkcp(sa + 16384, (const char*)g_h16p + (size_t)kt * 9216, 9216, fullb);
                    if (++pst == G1_NSTAGE) { pst = 0; pph ^= 1; }
                }
            }
            continue;
        }

        float acc[4][4];
#pragma unroll
        for (int t = 0; t < 4; t++) { acc[t][0] = acc[t][1] = acc[t][2] = acc[t][3] = 0.0f; }

        for (int kt = 0; kt < 64; kt++) {
            const uint32_t fullb = mb + cst * 8;
            const uint32_t emptyb = mb + (G1_NSTAGE + cst) * 8;
            mbar_wait_acq(fullb, cph);
            const uint32_t abase = smem0 + cst * G1_STAGE + a_qbase + aoff;
            const uint32_t bbase = smem0 + cst * G1_STAGE + 16384;
#pragma unroll
            for (int kk = 0; kk < 4; kk++) {
                unsigned a[4];
                ldsm4t_s(a[0], a[1], a[2], a[3], abase + kk * 2048);
                unsigned b[8];
                const uint32_t brow = bbase + (kk * 16 + b_k) * 144;
                ldsm4t_s(b[0], b[1], b[2], b[3], brow + (n_base + b_n) * 2);
                ldsm4t_s(b[4], b[5], b[6], b[7], brow + (n_base + 16 + b_n) * 2);
                mma16816(acc[0], a, b + 0);
                mma16816(acc[1], a, b + 2);
                mma16816(acc[2], a, b + 4);
                mma16816(acc[3], a, b + 6);
            }
            if (lane == 0) mbar_arrive(emptyb);
            if (++cst == G1_NSTAGE) { cst = 0; cph ^= 1; }
        }

        // epilogue: warp writes 16 rows x 32 cols
        const int cbase = n_base + 2 * (lane & 3);
        const int rrow = m0 + m_idx * 16 + (lane >> 2);
#pragma unroll
        for (int t = 0; t < 4; t++) {
            int n = cbase + t * 8;
            float b0 = ba[n], b1 = ba[n + 1];
            __half2 v0 = __floats2half2_rn(acc[t][0] * inv + b0, acc[t][1] * inv + b1);
            __half2 v1 = __floats2half2_rn(acc[t][2] * inv + b0, acc[t][3] * inv + b1);
            size_t base0 = ((size_t)e * NN + rrow) * HH + n;
            actp[base0 >> 1] = v0;
            actp[(base0 + 8 * HH) >> 1] = v1;
        }
    }
}

// ---------------- Update: S = sum_e act16[e]@W16[e] + h16@[uz|ur|0]; then gates ----------------
// m-tile 32 (grid 128), 8 warps x (16m x 48n), triple-buffered e-pipeline.
__global__ __launch_bounds__(256) void k_update(const int* __restrict__ d_it, int it,
                                                float* __restrict__ hio) {
    if (it >= d_it[0]) return;
    const int m0 = blockIdx.x * 32;
    extern __shared__ __align__(16) unsigned char upd[];

    const int tid = threadIdx.x, w = tid >> 5, lane = tid & 31;
    const int m_half = w & 1;            // 16 rows
    const int n_base = (w >> 1) * 48;    // 48 cols
    float acc[6][4];
#pragma unroll
    for (int t = 0; t < 6; t++) { acc[t][0] = acc[t][1] = acc[t][2] = acc[t][3] = 0.0f; }

    const int g = lane >> 3, r = lane & 7;
    const int a_row = m_half * 16 + (g & 1) * 8 + r;
    const int a_col = ((g >> 1) & 1) * 8;
    const int b_k = (g & 1) * 8 + r;
    const int b_nn = (g >> 1) * 8;

    auto load = [&](int e) {
        const int astride = (e < EE) ? 64 : 72;
        const __half* ag = (e < EE) ? g_act16 + ((size_t)e * NN + m0) * HH : g_h16p + (size_t)m0 * 72;
        const __half* bg = (e < EE) ? g_W16 + e * HH * NC : g_uzurpad16;
        unsigned char* buf = upd + (e % 3) * UP_BUF;
        __half (*As)[72]  = (__half(*)[72])buf;
        __half (*Bs)[200] = (__half(*)[200])(buf + UP_ABYTES);
        {   // A: 256 ops, 1 per thread
            int row = tid >> 3, ch = tid & 7;
            cp16(&As[row][ch * 8], ag + row * astride + ch * 8);
        }
        for (int c = tid; c < 1536; c += 256) {   // B: 6 per thread
            int row = c / 24, ch = c % 24;
            cp16(&Bs[row][ch * 8], bg + row * NC + ch * 8);
        }
        cp_commit();
    };

    load(0); load(1);
    for (int e = 0; e <= EE; e++) {
        if (e + 2 <= EE) { load(e + 2); cp_wait<2>(); }
        else if (e + 1 <= EE) { cp_wait<1>(); }
        else { cp_wait<0>(); }
        __syncthreads();
        const unsigned char* buf = upd + (e % 3) * UP_BUF;
        const __half (*As)[72]  = (const __half(*)[72])buf;
        const __half (*Bs)[200] = (const __half(*)[200])(buf + UP_ABYTES);
#pragma unroll
        for (int kk = 0; kk < 4; kk++) {
            unsigned a[4];
            ldsm4(a[0], a[1], a[2], a[3], &As[a_row][kk * 16 + a_col]);
#pragma unroll
            for (int p = 0; p < 3; p++) {
                unsigned b[4];
                ldsm4t(b[0], b[1], b[2], b[3], &Bs[kk * 16 + b_k][n_base + p * 16 + b_nn]);
                mma16816(acc[2 * p], a, b);
                mma16816(acc[2 * p + 1], a, b + 2);
            }
        }
        __syncthreads();
    }

    // write S tiles (fp32)
    {
        const int rrow = m0 + m_half * 16 + (lane >> 2);
        const int cb = n_base + 2 * (lane & 3);
        float2* sp = (float2*)g_S;
#pragma unroll
        for (int t = 0; t < 6; t++) {
            int n = cb + t * 8;
            sp[((size_t)rrow * NC + n) >> 1]       = make_float2(acc[t][0], acc[t][1]);
            sp[((size_t)(rrow + 8) * NC + n) >> 1] = make_float2(acc[t][2], acc[t][3]);
        }
    }
    __syncthreads();

    // ---- phase B: row-local gates (reuse smem) ----
    __half2* uh2 = (__half2*)upd;                      // 8192 B
    float (*rh_sm)[64] = (float(*)[64])(upd + 8192);   // 32*64*4 = 8192 B
    {
        const uint4* src = (const uint4*)g_uh16;
        uint4* dst = (uint4*)upd;
        for (int c = tid; c < 512; c += 256) dst[c] = src[c];
    }
    __syncthreads();

    const int c0 = 2 * lane;
    const int row0 = m0 + w * 4;       // each warp 4 rows
    float zz0[4], zz1[4], hv0[4], hv1[4];
#pragma unroll
    for (int q = 0; q < 4; q++) {
        int row = row0 + q;
        float2 s_z = *(const float2*)&g_S[(size_t)row * NC + c0];
        float2 t_z = *(const float2*)&g_T0[(size_t)row * NC + c0];
        float2 s_r = *(const float2*)&g_S[(size_t)row * NC + HH + c0];
        float2 t_r = *(const float2*)&g_T0[(size_t)row * NC + HH + c0];
        float2 h2  = *(const float2*)&hio[(size_t)row * HH + c0];
        float z0 = sigm(s_z.x + t_z.x), z1 = sigm(s_z.y + t_z.y);
        float r0v = sigm(s_r.x + t_r.x), r1v = sigm(s_r.y + t_r.y);
        zz0[q] = z0; zz1[q] = z1; hv0[q] = h2.x; hv1[q] = h2.y;
        rh_sm[w * 4 + q][c0] = r0v * h2.x;
        rh_sm[w * 4 + q][c0 + 1] = r1v * h2.y;
    }
    __syncwarp();

    float u0[4], u1[4];
#pragma unroll
    for (int q = 0; q < 4; q++) { u0[q] = 0.0f; u1[q] = 0.0f; }
#pragma unroll 4
    for (int i = 0; i < HH; i++) {
        float2 wv = __half22float2(uh2[i * 32 + lane]);
#pragma unroll
        for (int q = 0; q < 4; q++) {
            float rhv = rh_sm[w * 4 + q][i];
            u0[q] += rhv * wv.x;
            u1[q] += rhv * wv.y;
        }
    }

    __half2* h16pp = (__half2*)g_h16p;
#pragma unroll
    for (int q = 0; q < 4; q++) {
        int row = row0 + q;
        float2 s_h = *(const float2*)&g_S[(size_t)row * NC + 2 * HH + c0];
        float2 t_h = *(const float2*)&g_T0[(size_t)row * NC + 2 * HH + c0];
        float ht0 = tanh_fast(s_h.x + t_h.x + u0[q]);
        float ht1 = tanh_fast(s_h.y + t_h.y + u1[q]);
        float hn0 = hv0[q] + zz0[q] * (ht0 - hv0[q]);
        float hn1 = hv1[q] + zz1[q] * (ht1 - hv1[q]);
        *(float2*)&hio[(size_t)row * HH + c0] = make_float2(hn0, hn1);
        h16pp[((size_t)row * 72 + c0) >> 1] = __floats2half2_rn(hn0, hn1);
    }
}

// ---------------- launch ----------------
typedef CUresult (*EncodeFn)(CUtensorMap*, CUtensorMapDataType, cuuint32_t, void*,
                             const cuuint64_t*, const cuuint64_t*, const cuuint32_t*,
                             const cuuint32_t*, CUtensorMapInterleave, CUtensorMapSwizzle,
                             CUtensorMapL2promotion, CUtensorMapFloatOOBfill);

extern "C" void kernel_launch(void* const* d_in, const int* in_sizes, int n_in,
                              void* d_out, int out_size) {
    const float* input  = (const float*)d_in[0];
    const float* hidden = (const float*)d_in[1];
    const float* edge   = (const float*)d_in[2];
    const float* ba     = (const float*)d_in[3];
    const float* W      = (const float*)d_in[4];
    const float* uzur   = (const float*)d_in[5];
    const float* uh     = (const float*)d_in[6];
    const float* iwzrh  = (const float*)d_in[7];
    const int*   d_it   = (const int*)d_in[8];
    float* out = (float*)d_out;

    cudaFuncSetAttribute(k_gemm1, cudaFuncAttributeMaxDynamicSharedMemorySize, G1_SMEM);
    cudaFuncSetAttribute(k_update, cudaFuncAttributeMaxDynamicSharedMemorySize, UP_SMEM);

    // Tensormap for g_edge16 viewed as 3D [m=4096, k=4096, e=10], SW128, box 64x64x1
    CUtensorMap tma_a;
    {
        void* edge16_dev = nullptr;
        cudaGetSymbolAddress(&edge16_dev, g_edge16);
        EncodeFn enc = nullptr;
#if CUDART_VERSION >= 12000
        cudaDriverEntryPointQueryResult qres;
        cudaGetDriverEntryPoint("cuTensorMapEncodeTiled", (void**)&enc, cudaEnableDefault, &qres);
#else
        cudaGetDriverEntryPoint("cuTensorMapEncodeTiled", (void**)&enc, cudaEnableDefault);
#endif
        cuuint64_t dims[3]    = {NN, NN, EE};
        cuuint64_t strides[2] = {(cuuint64_t)NN * 2, (cuuint64_t)NN * NN * 2};
        cuuint32_t box[3]     = {64, 64, 1};
        cuuint32_t es[3]      = {1, 1, 1};
        if (enc) {
            enc(&tma_a, CU_TENSOR_MAP_DATA_TYPE_FLOAT16, 3, edge16_dev,
                dims, strides, box, es,
                CU_TENSOR_MAP_INTERLEAVE_NONE, CU_TENSOR_MAP_SWIZZLE_128B,
                CU_TENSOR_MAP_L2_PROMOTION_L2_128B, CU_TENSOR_MAP_FLOAT_OOB_FILL_NONE);
        }
    }

    k_conv_edge<<<8192, 256>>>(edge);
    k_setup<<<(NN * HH + 255) / 256, 256>>>(hidden, W, uzur, uh, out);
    k_t0<<<NN, NC>>>(input, iwzrh);

    for (int it = 0; it < 10; ++it) {
        k_gemm1<<<G1_GRID, 544, G1_SMEM>>>(d_it, it, ba, tma_a);
        k_update<<<NN / 32, 256, UP_SMEM>>>(d_it, it, out);
    }
}

// round 11
// speedup vs baseline: 1.0183x; 1.0183x over previous
#include <cuda_runtime.h>
#include <cuda.h>
#include <cuda_fp16.h>
#include <cstdint>
#include <cstddef>

#define NN 4096
#define HH 64
#define EE 10
#define NC 192   // 3*H

// gemm1: persistent, BM=64, BK=64, 5-stage TMA pipeline, work-steal 640 items
#define G1_NSTAGE 5
#define G1_STAGE 17408            // A: 8192 (SW128 64x64 tile) + B: 9216 (64 rows x 144B)
#define G1_SMEM (G1_NSTAGE * G1_STAGE + 1024)
#define G1_ITEMS 640              // 64 m-tiles x 10 edge types
#define G1_GRID 148

// update: m-tile 32, triple-buffered e-pipeline
#define UP_ABYTES 4608            // 32 rows x 144B
#define UP_BBYTES 25600           // 64 rows x 400B
#define UP_BUF (UP_ABYTES + UP_BBYTES)   // 30208
#define UP_SMEM (3 * UP_BUF)             // 90624

// ---------------- scratch (device globals; no allocations allowed) ----------------
__device__ __half g_edge16[(size_t)EE * NN * NN];   // 335 MB, edge * 4096 in fp16, [e][k][m]
__device__ __half g_h16p[NN * 72];                  // hidden fp16, padded rows (144 B)
__device__ __half g_act16[(size_t)EE * NN * HH];    // per-edge aggregated messages
__device__ __half g_W16[EE * HH * NC];              // wz_wr_wh in fp16
__device__ __half g_uzurpad16[HH * NC];             // [uz|ur|0] padded to 192 cols
__device__ __half g_uh16[HH * HH];                  // uh in fp16
__device__ float  g_T0[NN * NC];                    // E * (input @ input_wzrh)
__device__ float  g_S[NN * NC];                     // gate pre-activations
__device__ int    g_ctr1[16];                       // per-iteration work-steal counters

// ---------------- PTX helpers ----------------
__device__ __forceinline__ void cp16(void* s, const void* g) {
    unsigned sa = (unsigned)__cvta_generic_to_shared(s);
    asm volatile("cp.async.cg.shared.global [%0], [%1], 16;" :: "r"(sa), "l"(g));
}
__device__ __forceinline__ void cp_commit() { asm volatile("cp.async.commit_group;"); }
template <int N_>
__device__ __forceinline__ void cp_wait() { asm volatile("cp.async.wait_group %0;" :: "n"(N_)); }

__device__ __forceinline__ void bulkcp(uint32_t dst, const void* src, uint32_t bytes, uint32_t mbar) {
    asm volatile("cp.async.bulk.shared::cta.global.mbarrier::complete_tx::bytes [%0], [%1], %2, [%3];"
                 :: "r"(dst), "l"(src), "r"(bytes), "r"(mbar) : "memory");
}
__device__ __forceinline__ void tma3d(uint32_t dst, const CUtensorMap* map,
                                      int x, int y, int z, uint32_t mbar) {
    asm volatile("cp.async.bulk.tensor.3d.shared::cta.global.tile.mbarrier::complete_tx::bytes "
                 "[%0], [%1, {%2, %3, %4}], [%5];"
                 :: "r"(dst), "l"(map), "r"(x), "r"(y), "r"(z), "r"(mbar) : "memory");
}
__device__ __forceinline__ void mbar_init(uint32_t mbar, uint32_t count) {
    asm volatile("mbarrier.init.shared.b64 [%0], %1;" :: "r"(mbar), "r"(count) : "memory");
}
__device__ __forceinline__ void mbar_expect_tx(uint32_t mbar, uint32_t bytes) {
    asm volatile("mbarrier.arrive.expect_tx.shared.b64 _, [%0], %1;" :: "r"(mbar), "r"(bytes) : "memory");
}
__device__ __forceinline__ void mbar_arrive(uint32_t mbar) {
    asm volatile("mbarrier.arrive.shared.b64 _, [%0];" :: "r"(mbar) : "memory");
}
__device__ __forceinline__ void mbar_wait_acq(uint32_t mbar, uint32_t parity) {
    asm volatile(
        "{\n\t.reg .pred P1;\n\t"
        "WAIT_LOOP_%=:\n\t"
        "mbarrier.try_wait.parity.acquire.cta.shared::cta.b64 P1, [%0], %1, 0x989680;\n\t"
        "@P1 bra.uni WAIT_DONE_%=;\n\t"
        "bra.uni WAIT_LOOP_%=;\n\t"
        "WAIT_DONE_%=:\n\t}"
        :: "r"(mbar), "r"(parity) : "memory");
}
__device__ __forceinline__ void mbar_wait_rlx(uint32_t mbar, uint32_t parity) {
    asm volatile(
        "{\n\t.reg .pred P1;\n\t"
        "WAIT_LOOP_%=:\n\t"
        "mbarrier.try_wait.parity.relaxed.cta.shared::cta.b64 P1, [%0], %1, 0x989680;\n\t"
        "@P1 bra.uni WAIT_DONE_%=;\n\t"
        "bra.uni WAIT_LOOP_%=;\n\t"
        "WAIT_DONE_%=:\n\t}"
        :: "r"(mbar), "r"(parity) : "memory");
}

// trans ldmatrix (operand stored [k][major])
__device__ __forceinline__ void ldsm4t(unsigned& r0, unsigned& r1, unsigned& r2, unsigned& r3,
                                       const void* p) {
    unsigned a = (unsigned)__cvta_generic_to_shared(p);
    asm volatile("ldmatrix.sync.aligned.m8n8.x4.trans.shared.b16 {%0,%1,%2,%3}, [%4];"
                 : "=r"(r0), "=r"(r1), "=r"(r2), "=r"(r3) : "r"(a));
}
__device__ __forceinline__ void ldsm4t_s(unsigned& r0, unsigned& r1, unsigned& r2, unsigned& r3,
                                         uint32_t a) {
    asm volatile("ldmatrix.sync.aligned.m8n8.x4.trans.shared.b16 {%0,%1,%2,%3}, [%4];"
                 : "=r"(r0), "=r"(r1), "=r"(r2), "=r"(r3) : "r"(a));
}
// non-trans ldmatrix (A stored row-major [m][k])
__device__ __forceinline__ void ldsm4(unsigned& r0, unsigned& r1, unsigned& r2, unsigned& r3,
                                      const void* p) {
    unsigned a = (unsigned)__cvta_generic_to_shared(p);
    asm volatile("ldmatrix.sync.aligned.m8n8.x4.shared.b16 {%0,%1,%2,%3}, [%4];"
                 : "=r"(r0), "=r"(r1), "=r"(r2), "=r"(r3) : "r"(a));
}
__device__ __forceinline__ void mma16816(float* c, const unsigned* a, const unsigned* b) {
    asm volatile(
        "mma.sync.aligned.m16n8k16.row.col.f32.f16.f16.f32 "
        "{%0,%1,%2,%3},{%4,%5,%6,%7},{%8,%9},{%0,%1,%2,%3};"
        : "+f"(c[0]), "+f"(c[1]), "+f"(c[2]), "+f"(c[3])
        : "r"(a[0]), "r"(a[1]), "r"(a[2]), "r"(a[3]), "r"(b[0]), "r"(b[1]));
}

__device__ __forceinline__ float sigm(float x) { return 1.0f / (1.0f + __expf(-x)); }
__device__ __forceinline__ float tanh_fast(float x) { return 2.0f / (1.0f + __expf(-2.0f * x)) - 1.0f; }

// ---------------- setup kernels ----------------
__global__ void k_conv_edge(const float* __restrict__ edge) {
    const size_t n8 = (size_t)EE * NN * NN / 8;
    const float4* src = (const float4*)edge;
    uint4* dst = (uint4*)g_edge16;
    for (size_t i = (size_t)blockIdx.x * blockDim.x + threadIdx.x; i < n8;
         i += (size_t)gridDim.x * blockDim.x) {
        float4 a = src[2 * i];
        float4 b = src[2 * i + 1];
        __half2 h0 = __floats2half2_rn(a.x * 4096.0f, a.y * 4096.0f);
        __half2 h1 = __floats2half2_rn(a.z * 4096.0f, a.w * 4096.0f);
        __half2 h2 = __floats2half2_rn(b.x * 4096.0f, b.y * 4096.0f);
        __half2 h3 = __floats2half2_rn(b.z * 4096.0f, b.w * 4096.0f);
        uint4 o;
        o.x = *(unsigned*)&h0; o.y = *(unsigned*)&h1;
        o.z = *(unsigned*)&h2; o.w = *(unsigned*)&h3;
        dst[i] = o;
    }
}

__global__ void k_setup(const float* __restrict__ hidden, const float* __restrict__ W,
                        const float* __restrict__ uzur, const float* __restrict__ uh,
                        float* __restrict__ dout) {
    int i = blockIdx.x * blockDim.x + threadIdx.x;   // grid covers 262144
    if (i < 16) g_ctr1[i] = 0;
    if (i < NN * HH) {
        float v = hidden[i]; dout[i] = v;
        g_h16p[(i >> 6) * 72 + (i & 63)] = __float2half_rn(v);
    }
    if (i < EE * HH * NC) g_W16[i] = __float2half_rn(W[i]);
    if (i < HH * NC) {
        int r = i / NC, c = i % NC;
        g_uzurpad16[i] = __float2half_rn(c < 2 * HH ? uzur[r * 2 * HH + c] : 0.0f);
    }
    if (i < HH * HH) g_uh16[i] = __float2half_rn(uh[i]);
}

__global__ void k_t0(const float* __restrict__ input, const float* __restrict__ iwzrh) {
    __shared__ float xs[HH];
    int row = blockIdx.x;
    int j = threadIdx.x;  // 0..191
    if (j < HH) xs[j] = input[row * HH + j];
    __syncthreads();
    float acc = 0.0f;
#pragma unroll 8
    for (int i = 0; i < HH; i++) acc += xs[i] * iwzrh[i * NC + j];
    g_T0[row * NC + j] = (float)EE * acc;
}

// ---------------- GEMM1 (persistent): act16[e] = edge[e]^T @ h + ba ----------------
// 148 CTAs x 288 threads: 8 consumer warps (32m x 16n each) + 1 producer warp.
// BM=64, work-steal 640 items. Per stage: 1 TMA 64x64 SW128 A tile + 9216B bulk B.
__global__ __launch_bounds__(288, 1) void k_gemm1(const int* __restrict__ d_it, int it,
                                                  const float* __restrict__ ba,
                                                  const __grid_constant__ CUtensorMap tma_a) {
    if (it >= d_it[0]) return;
    extern __shared__ unsigned char dsm_raw[];
    __shared__ __align__(8) unsigned long long mbar_sto[2 * G1_NSTAGE];
    __shared__ int s_item;
    const uint32_t smem0 = ((uint32_t)__cvta_generic_to_shared(dsm_raw) + 1023u) & ~1023u;
    const uint32_t mb = (uint32_t)__cvta_generic_to_shared(mbar_sto);
    const int tid = threadIdx.x, w = tid >> 5, lane = tid & 31;

    if (tid == 0) {
        for (int s = 0; s < G1_NSTAGE; s++) {
            mbar_init(mb + s * 8, 1);                    // full: expect_tx arrival
            mbar_init(mb + (G1_NSTAGE + s) * 8, 8);      // empty: 8 consumer warps
        }
    }

    // consumer fragment addressing (item-invariant)
    const int mg = w & 1;                // m-group: 32m
    const int n_base = (w >> 1) * 16;    // n-group: 16n  (w>>1 in 0..3)
    const int g = lane >> 3, r = lane & 7;
    const int a_k = ((g >> 1) & 1) * 8 + r;
    uint32_t aoff[2];
#pragma unroll
    for (int j = 0; j < 2; j++)
        aoff[j] = (uint32_t)((a_k * 128 + ((mg * 2 + j) * 16 + (g & 1) * 8) * 2) ^ (r << 4));
    const int b_k = (g & 1) * 8 + r;
    const int b_n = (g >> 1) * 8;
    const float inv = 1.0f / 4096.0f;
    __half2* actp = (__half2*)g_act16;

    // pipeline state persists across items
    int pst = 0, pph = 1;     // producer
    int cst = 0, cph = 0;     // consumer

    for (;;) {
        __syncthreads();
        if (tid == 0) s_item = atomicAdd(&g_ctr1[it], 1);
        __syncthreads();
        const int item = s_item;
        if (item >= G1_ITEMS) break;
        const int e = item >> 6;
        const int m0 = (item & 63) * 64;

        if (w == 8) {
            if (lane == 0) {
                for (int kt = 0; kt < 64; kt++) {
                    const uint32_t fullb = mb + pst * 8;
                    const uint32_t emptyb = mb + (G1_NSTAGE + pst) * 8;
                    mbar_wait_rlx(emptyb, pph);
                    mbar_expect_tx(fullb, G1_STAGE);
                    const uint32_t sa = smem0 + pst * G1_STAGE;
                    tma3d(sa, &tma_a, m0, kt * 64, e, fullb);
                    bulkcp(sa + 8192, (const char*)g_h16p + (size_t)kt * 9216, 9216, fullb);
                    if (++pst == G1_NSTAGE) { pst = 0; pph ^= 1; }
                }
            }
            continue;
        }

        float acc[2][2][4];
#pragma unroll
        for (int j = 0; j < 2; j++)
#pragma unroll
            for (int p = 0; p < 2; p++) {
                acc[j][p][0] = acc[j][p][1] = acc[j][p][2] = acc[j][p][3] = 0.0f;
            }

        for (int kt = 0; kt < 64; kt++) {
            const uint32_t fullb = mb + cst * 8;
            const uint32_t emptyb = mb + (G1_NSTAGE + cst) * 8;
            mbar_wait_acq(fullb, cph);
            const uint32_t abase = smem0 + cst * G1_STAGE;
            const uint32_t bbase = abase + 8192;

            // prefetch ALL B fragments for the stage (4 kk x 16n)
            unsigned bf[4][4];
#pragma unroll
            for (int kk = 0; kk < 4; kk++)
                ldsm4t_s(bf[kk][0], bf[kk][1], bf[kk][2], bf[kk][3],
                         bbase + (kk * 16 + b_k) * 144 + (n_base + b_n) * 2);

            // A fragments: double-buffered across kk
            unsigned af[2][2][4];
#pragma unroll
            for (int j = 0; j < 2; j++)
                ldsm4t_s(af[0][j][0], af[0][j][1], af[0][j][2], af[0][j][3],
                         abase + aoff[j]);
#pragma unroll
            for (int kk = 0; kk < 4; kk++) {
                const int cur = kk & 1;
                if (kk < 3) {
#pragma unroll
                    for (int j = 0; j < 2; j++)
                        ldsm4t_s(af[cur ^ 1][j][0], af[cur ^ 1][j][1],
                                 af[cur ^ 1][j][2], af[cur ^ 1][j][3],
                                 abase + aoff[j] + (kk + 1) * 2048);
                }
#pragma unroll
                for (int j = 0; j < 2; j++) {
                    mma16816(acc[j][0], af[cur][j], bf[kk] + 0);
                    mma16816(acc[j][1], af[cur][j], bf[kk] + 2);
                }
            }
            if (lane == 0) mbar_arrive(emptyb);
            if (++cst == G1_NSTAGE) { cst = 0; cph ^= 1; }
        }

        // epilogue: warp writes 32 rows x 16 cols
        const int cb = 2 * (lane & 3);
#pragma unroll
        for (int j = 0; j < 2; j++) {
            const int rrow = m0 + mg * 32 + j * 16 + (lane >> 2);
#pragma unroll
            for (int p = 0; p < 2; p++) {
                const int n = n_base + p * 8 + cb;
                float b0 = ba[n], b1 = ba[n + 1];
                __half2 v0 = __floats2half2_rn(acc[j][p][0] * inv + b0, acc[j][p][1] * inv + b1);
                __half2 v1 = __floats2half2_rn(acc[j][p][2] * inv + b0, acc[j][p][3] * inv + b1);
                size_t base0 = ((size_t)e * NN + rrow) * HH + n;
                actp[base0 >> 1] = v0;
                actp[(base0 + 8 * HH) >> 1] = v1;
            }
        }
    }
}

// ---------------- Update: S = sum_e act16[e]@W16[e] + h16@[uz|ur|0]; then gates ----------------
// m-tile 32 (grid 128), 8 warps x (16m x 48n), triple-buffered e-pipeline.
__global__ __launch_bounds__(256) void k_update(const int* __restrict__ d_it, int it,
                                                float* __restrict__ hio) {
    if (it >= d_it[0]) return;
    const int m0 = blockIdx.x * 32;
    extern __shared__ __align__(16) unsigned char upd[];

    const int tid = threadIdx.x, w = tid >> 5, lane = tid & 31;
    const int m_half = w & 1;            // 16 rows
    const int n_base = (w >> 1) * 48;    // 48 cols
    float acc[6][4];
#pragma unroll
    for (int t = 0; t < 6; t++) { acc[t][0] = acc[t][1] = acc[t][2] = acc[t][3] = 0.0f; }

    const int g = lane >> 3, r = lane & 7;
    const int a_row = m_half * 16 + (g & 1) * 8 + r;
    const int a_col = ((g >> 1) & 1) * 8;
    const int b_k = (g & 1) * 8 + r;
    const int b_nn = (g >> 1) * 8;

    auto load = [&](int e) {
        const int astride = (e < EE) ? 64 : 72;
        const __half* ag = (e < EE) ? g_act16 + ((size_t)e * NN + m0) * HH : g_h16p + (size_t)m0 * 72;
        const __half* bg = (e < EE) ? g_W16 + e * HH * NC : g_uzurpad16;
        unsigned char* buf = upd + (e % 3) * UP_BUF;
        __half (*As)[72]  = (__half(*)[72])buf;
        __half (*Bs)[200] = (__half(*)[200])(buf + UP_ABYTES);
        {   // A: 256 ops, 1 per thread
            int row = tid >> 3, ch = tid & 7;
            cp16(&As[row][ch * 8], ag + row * astride + ch * 8);
        }
        for (int c = tid; c < 1536; c += 256) {   // B: 6 per thread
            int row = c / 24, ch = c % 24;
            cp16(&Bs[row][ch * 8], bg + row * NC + ch * 8);
        }
        cp_commit();
    };

    load(0); load(1);
    for (int e = 0; e <= EE; e++) {
        if (e + 2 <= EE) { load(e + 2); cp_wait<2>(); }
        else if (e + 1 <= EE) { cp_wait<1>(); }
        else { cp_wait<0>(); }
        __syncthreads();
        const unsigned char* buf = upd + (e % 3) * UP_BUF;
        const __half (*As)[72]  = (const __half(*)[72])buf;
        const __half (*Bs)[200] = (const __half(*)[200])(buf + UP_ABYTES);
#pragma unroll
        for (int kk = 0; kk < 4; kk++) {
            unsigned a[4];
            ldsm4(a[0], a[1], a[2], a[3], &As[a_row][kk * 16 + a_col]);
#pragma unroll
            for (int p = 0; p < 3; p++) {
                unsigned b[4];
                ldsm4t(b[0], b[1], b[2], b[3], &Bs[kk * 16 + b_k][n_base + p * 16 + b_nn]);
                mma16816(acc[2 * p], a, b);
                mma16816(acc[2 * p + 1], a, b + 2);
            }
        }
        __syncthreads();
    }

    // write S tiles (fp32)
    {
        const int rrow = m0 + m_half * 16 + (lane >> 2);
        const int cb = n_base + 2 * (lane & 3);
        float2* sp = (float2*)g_S;
#pragma unroll
        for (int t = 0; t < 6; t++) {
            int n = cb + t * 8;
            sp[((size_t)rrow * NC + n) >> 1]       = make_float2(acc[t][0], acc[t][1]);
            sp[((size_t)(rrow + 8) * NC + n) >> 1] = make_float2(acc[t][2], acc[t][3]);
        }
    }
    __syncthreads();

    // ---- phase B: row-local gates (reuse smem) ----
    __half2* uh2 = (__half2*)upd;                      // 8192 B
    float (*rh_sm)[64] = (float(*)[64])(upd + 8192);   // 32*64*4 = 8192 B
    {
        const uint4* src = (const uint4*)g_uh16;
        uint4* dst = (uint4*)upd;
        for (int c = tid; c < 512; c += 256) dst[c] = src[c];
    }
    __syncthreads();

    const int c0 = 2 * lane;
    const int row0 = m0 + w * 4;       // each warp 4 rows
    float zz0[4], zz1[4], hv0[4], hv1[4];
#pragma unroll
    for (int q = 0; q < 4; q++) {
        int row = row0 + q;
        float2 s_z = *(const float2*)&g_S[(size_t)row * NC + c0];
        float2 t_z = *(const float2*)&g_T0[(size_t)row * NC + c0];
        float2 s_r = *(const float2*)&g_S[(size_t)row * NC + HH + c0];
        float2 t_r = *(const float2*)&g_T0[(size_t)row * NC + HH + c0];
        float2 h2  = *(const float2*)&hio[(size_t)row * HH + c0];
        float z0 = sigm(s_z.x + t_z.x), z1 = sigm(s_z.y + t_z.y);
        float r0v = sigm(s_r.x + t_r.x), r1v = sigm(s_r.y + t_r.y);
        zz0[q] = z0; zz1[q] = z1; hv0[q] = h2.x; hv1[q] = h2.y;
        rh_sm[w * 4 + q][c0] = r0v * h2.x;
        rh_sm[w * 4 + q][c0 + 1] = r1v * h2.y;
    }
    __syncwarp();

    float u0[4], u1[4];
#pragma unroll
    for (int q = 0; q < 4; q++) { u0[q] = 0.0f; u1[q] = 0.0f; }
#pragma unroll 4
    for (int i = 0; i < HH; i++) {
        float2 wv = __half22float2(uh2[i * 32 + lane]);
#pragma unroll
        for (int q = 0; q < 4; q++) {
            float rhv = rh_sm[w * 4 + q][i];
            u0[q] += rhv * wv.x;
            u1[q] += rhv * wv.y;
        }
    }

    __half2* h16pp = (__half2*)g_h16p;
#pragma unroll
    for (int q = 0; q < 4; q++) {
        int row = row0 + q;
        float2 s_h = *(const float2*)&g_S[(size_t)row * NC + 2 * HH + c0];
        float2 t_h = *(const float2*)&g_T0[(size_t)row * NC + 2 * HH + c0];
        float ht0 = tanh_fast(s_h.x + t_h.x + u0[q]);
        float ht1 = tanh_fast(s_h.y + t_h.y + u1[q]);
        float hn0 = hv0[q] + zz0[q] * (ht0 - hv0[q]);
        float hn1 = hv1[q] + zz1[q] * (ht1 - hv1[q]);
        *(float2*)&hio[(size_t)row * HH + c0] = make_float2(hn0, hn1);
        h16pp[((size_t)row * 72 + c0) >> 1] = __floats2half2_rn(hn0, hn1);
    }
}

// ---------------- launch ----------------
typedef CUresult (*EncodeFn)(CUtensorMap*, CUtensorMapDataType, cuuint32_t, void*,
                             const cuuint64_t*, const cuuint64_t*, const cuuint32_t*,
                             const cuuint32_t*, CUtensorMapInterleave, CUtensorMapSwizzle,
                             CUtensorMapL2promotion, CUtensorMapFloatOOBfill);

extern "C" void kernel_launch(void* const* d_in, const int* in_sizes, int n_in,
                              void* d_out, int out_size) {
    const float* input  = (const float*)d_in[0];
    const float* hidden = (const float*)d_in[1];
    const float* edge   = (const float*)d_in[2];
    const float* ba     = (const float*)d_in[3];
    const float* W      = (const float*)d_in[4];
    const float* uzur   = (const float*)d_in[5];
    const float* uh     = (const float*)d_in[6];
    const float* iwzrh  = (const float*)d_in[7];
    const int*   d_it   = (const int*)d_in[8];
    float* out = (float*)d_out;

    cudaFuncSetAttribute(k_gemm1, cudaFuncAttributeMaxDynamicSharedMemorySize, G1_SMEM);
    cudaFuncSetAttribute(k_update, cudaFuncAttributeMaxDynamicSharedMemorySize, UP_SMEM);

    // Tensormap for g_edge16 viewed as 3D [m=4096 (inner), k=4096, e=10], SW128, box 64x64x1
    CUtensorMap tma_a;
    {
        void* edge16_dev = nullptr;
        cudaGetSymbolAddress(&edge16_dev, g_edge16);
        EncodeFn enc = nullptr;
#if CUDART_VERSION >= 12000
        cudaDriverEntryPointQueryResult qres;
        cudaGetDriverEntryPoint("cuTensorMapEncodeTiled", (void**)&enc, cudaEnableDefault, &qres);
#else
        cudaGetDriverEntryPoint("cuTensorMapEncodeTiled", (void**)&enc, cudaEnableDefault);
#endif
        cuuint64_t dims[3]    = {NN, NN, EE};
        cuuint64_t strides[2] = {(cuuint64_t)NN * 2, (cuuint64_t)NN * NN * 2};
        cuuint32_t box[3]     = {64, 64, 1};
        cuuint32_t es[3]      = {1, 1, 1};
        if (enc) {
            enc(&tma_a, CU_TENSOR_MAP_DATA_TYPE_FLOAT16, 3, edge16_dev,
                dims, strides, box, es,
                CU_TENSOR_MAP_INTERLEAVE_NONE, CU_TENSOR_MAP_SWIZZLE_128B,
                CU_TENSOR_MAP_L2_PROMOTION_L2_128B, CU_TENSOR_MAP_FLOAT_OOB_FILL_NONE);
        }
    }

    k_conv_edge<<<8192, 256>>>(edge);
    k_setup<<<(NN * HH + 255) / 256, 256>>>(hidden, W, uzur, uh, out);
    k_t0<<<NN, NC>>>(input, iwzrh);

    for (int it = 0; it < 10; ++it) {
        k_gemm1<<<G1_GRID, 288, G1_SMEM>>>(d_it, it, ba, tma_a);
        k_update<<<NN / 32, 256, UP_SMEM>>>(d_it, it, out);
    }
}

// round 12
// speedup vs baseline: 1.1920x; 1.1706x over previous
#include <cuda_runtime.h>
#include <cuda.h>
#include <cuda_fp16.h>
#include <cstdint>
#include <cstddef>

#define NN 4096
#define HH 64
#define EE 10
#define NC 192   // 3*H

// gemm1: persistent, BM=128, BK=64, 4-stage TMA pipeline, work-stealing over 320 items
// 2 CTAs per SM (102KB smem each) for cross-CTA latency hiding.
#define G1_NSTAGE 4
#define G1_STAGE 25600            // A: 2*8192 (SW128 64x64 tiles) + B: 9216 (64 rows x 144B)
#define G1_SMEM (G1_NSTAGE * G1_STAGE + 1024)
#define G1_ITEMS 320              // 32 m-tiles x 10 edge types
#define G1_GRID 296               // 2 persistent CTAs per SM

// update: m-tile 32, triple-buffered e-pipeline
#define UP_ABYTES 4608            // 32 rows x 144B
#define UP_BBYTES 25600           // 64 rows x 400B
#define UP_BUF (UP_ABYTES + UP_BBYTES)   // 30208
#define UP_SMEM (3 * UP_BUF)             // 90624

// ---------------- scratch (device globals; no allocations allowed) ----------------
__device__ __half g_edge16[(size_t)EE * NN * NN];   // 335 MB, edge * 4096 in fp16, [e][k][m]
__device__ __half g_h16p[NN * 72];                  // hidden fp16, padded rows (144 B)
__device__ __half g_act16[(size_t)EE * NN * HH];    // per-edge aggregated messages
__device__ __half g_W16[EE * HH * NC];              // wz_wr_wh in fp16
__device__ __half g_uzurpad16[HH * NC];             // [uz|ur|0] padded to 192 cols
__device__ __half g_uh16[HH * HH];                  // uh in fp16
__device__ float  g_T0[NN * NC];                    // E * (input @ input_wzrh)
__device__ float  g_S[NN * NC];                     // gate pre-activations
__device__ int    g_ctr1[16];                       // per-iteration work-steal counters

// ---------------- PTX helpers ----------------
__device__ __forceinline__ void cp16(void* s, const void* g) {
    unsigned sa = (unsigned)__cvta_generic_to_shared(s);
    asm volatile("cp.async.cg.shared.global [%0], [%1], 16;" :: "r"(sa), "l"(g));
}
__device__ __forceinline__ void cp_commit() { asm volatile("cp.async.commit_group;"); }
template <int N_>
__device__ __forceinline__ void cp_wait() { asm volatile("cp.async.wait_group %0;" :: "n"(N_)); }

__device__ __forceinline__ void bulkcp(uint32_t dst, const void* src, uint32_t bytes, uint32_t mbar) {
    asm volatile("cp.async.bulk.shared::cta.global.mbarrier::complete_tx::bytes [%0], [%1], %2, [%3];"
                 :: "r"(dst), "l"(src), "r"(bytes), "r"(mbar) : "memory");
}
__device__ __forceinline__ void tma3d(uint32_t dst, const CUtensorMap* map,
                                      int x, int y, int z, uint32_t mbar) {
    asm volatile("cp.async.bulk.tensor.3d.shared::cta.global.tile.mbarrier::complete_tx::bytes "
                 "[%0], [%1, {%2, %3, %4}], [%5];"
                 :: "r"(dst), "l"(map), "r"(x), "r"(y), "r"(z), "r"(mbar) : "memory");
}
__device__ __forceinline__ void mbar_init(uint32_t mbar, uint32_t count) {
    asm volatile("mbarrier.init.shared.b64 [%0], %1;" :: "r"(mbar), "r"(count) : "memory");
}
__device__ __forceinline__ void mbar_expect_tx(uint32_t mbar, uint32_t bytes) {
    asm volatile("mbarrier.arrive.expect_tx.shared.b64 _, [%0], %1;" :: "r"(mbar), "r"(bytes) : "memory");
}
__device__ __forceinline__ void mbar_arrive(uint32_t mbar) {
    asm volatile("mbarrier.arrive.shared.b64 _, [%0];" :: "r"(mbar) : "memory");
}
__device__ __forceinline__ void mbar_wait_acq(uint32_t mbar, uint32_t parity) {
    asm volatile(
        "{\n\t.reg .pred P1;\n\t"
        "WAIT_LOOP_%=:\n\t"
        "mbarrier.try_wait.parity.acquire.cta.shared::cta.b64 P1, [%0], %1, 0x989680;\n\t"
        "@P1 bra.uni WAIT_DONE_%=;\n\t"
        "bra.uni WAIT_LOOP_%=;\n\t"
        "WAIT_DONE_%=:\n\t}"
        :: "r"(mbar), "r"(parity) : "memory");
}
__device__ __forceinline__ void mbar_wait_rlx(uint32_t mbar, uint32_t parity) {
    asm volatile(
        "{\n\t.reg .pred P1;\n\t"
        "WAIT_LOOP_%=:\n\t"
        "mbarrier.try_wait.parity.relaxed.cta.shared::cta.b64 P1, [%0], %1, 0x989680;\n\t"
        "@P1 bra.uni WAIT_DONE_%=;\n\t"
        "bra.uni WAIT_LOOP_%=;\n\t"
        "WAIT_DONE_%=:\n\t}"
        :: "r"(mbar), "r"(parity) : "memory");
}

// trans ldmatrix (operand stored [k][major])
__device__ __forceinline__ void ldsm4t(unsigned& r0, unsigned& r1, unsigned& r2, unsigned& r3,
                                       const void* p) {
    unsigned a = (unsigned)__cvta_generic_to_shared(p);
    asm volatile("ldmatrix.sync.aligned.m8n8.x4.trans.shared.b16 {%0,%1,%2,%3}, [%4];"
                 : "=r"(r0), "=r"(r1), "=r"(r2), "=r"(r3) : "r"(a));
}
__device__ __forceinline__ void ldsm4t_s(unsigned& r0, unsigned& r1, unsigned& r2, unsigned& r3,
                                         uint32_t a) {
    asm volatile("ldmatrix.sync.aligned.m8n8.x4.trans.shared.b16 {%0,%1,%2,%3}, [%4];"
                 : "=r"(r0), "=r"(r1), "=r"(r2), "=r"(r3) : "r"(a));
}
// non-trans ldmatrix (A stored row-major [m][k])
__device__ __forceinline__ void ldsm4(unsigned& r0, unsigned& r1, unsigned& r2, unsigned& r3,
                                      const void* p) {
    unsigned a = (unsigned)__cvta_generic_to_shared(p);
    asm volatile("ldmatrix.sync.aligned.m8n8.x4.shared.b16 {%0,%1,%2,%3}, [%4];"
                 : "=r"(r0), "=r"(r1), "=r"(r2), "=r"(r3) : "r"(a));
}
__device__ __forceinline__ void mma16816(float* c, const unsigned* a, const unsigned* b) {
    asm volatile(
        "mma.sync.aligned.m16n8k16.row.col.f32.f16.f16.f32 "
        "{%0,%1,%2,%3},{%4,%5,%6,%7},{%8,%9},{%0,%1,%2,%3};"
        : "+f"(c[0]), "+f"(c[1]), "+f"(c[2]), "+f"(c[3])
        : "r"(a[0]), "r"(a[1]), "r"(a[2]), "r"(a[3]), "r"(b[0]), "r"(b[1]));
}

__device__ __forceinline__ float sigm(float x) { return 1.0f / (1.0f + __expf(-x)); }
__device__ __forceinline__ float tanh_fast(float x) { return 2.0f / (1.0f + __expf(-2.0f * x)) - 1.0f; }

// ---------------- setup kernels ----------------
__global__ void k_conv_edge(const float* __restrict__ edge) {
    const size_t n8 = (size_t)EE * NN * NN / 8;
    const float4* src = (const float4*)edge;
    uint4* dst = (uint4*)g_edge16;
    for (size_t i = (size_t)blockIdx.x * blockDim.x + threadIdx.x; i < n8;
         i += (size_t)gridDim.x * blockDim.x) {
        float4 a = src[2 * i];
        float4 b = src[2 * i + 1];
        __half2 h0 = __floats2half2_rn(a.x * 4096.0f, a.y * 4096.0f);
        __half2 h1 = __floats2half2_rn(a.z * 4096.0f, a.w * 4096.0f);
        __half2 h2 = __floats2half2_rn(b.x * 4096.0f, b.y * 4096.0f);
        __half2 h3 = __floats2half2_rn(b.z * 4096.0f, b.w * 4096.0f);
        uint4 o;
        o.x = *(unsigned*)&h0; o.y = *(unsigned*)&h1;
        o.z = *(unsigned*)&h2; o.w = *(unsigned*)&h3;
        dst[i] = o;
    }
}

__global__ void k_setup(const float* __restrict__ hidden, const float* __restrict__ W,
                        const float* __restrict__ uzur, const float* __restrict__ uh,
                        float* __restrict__ dout) {
    int i = blockIdx.x * blockDim.x + threadIdx.x;   // grid covers 262144
    if (i < 16) g_ctr1[i] = 0;
    if (i < NN * HH) {
        float v = hidden[i]; dout[i] = v;
        g_h16p[(i >> 6) * 72 + (i & 63)] = __float2half_rn(v);
    }
    if (i < EE * HH * NC) g_W16[i] = __float2half_rn(W[i]);
    if (i < HH * NC) {
        int r = i / NC, c = i % NC;
        g_uzurpad16[i] = __float2half_rn(c < 2 * HH ? uzur[r * 2 * HH + c] : 0.0f);
    }
    if (i < HH * HH) g_uh16[i] = __float2half_rn(uh[i]);
}

__global__ void k_t0(const float* __restrict__ input, const float* __restrict__ iwzrh) {
    __shared__ float xs[HH];
    int row = blockIdx.x;
    int j = threadIdx.x;  // 0..191
    if (j < HH) xs[j] = input[row * HH + j];
    __syncthreads();
    float acc = 0.0f;
#pragma unroll 8
    for (int i = 0; i < HH; i++) acc += xs[i] * iwzrh[i * NC + j];
    g_T0[row * NC + j] = (float)EE * acc;
}

// ---------------- GEMM1 (persistent): act16[e] = edge[e]^T @ h + ba ----------------
// 296 CTAs (2/SM), work-steal 320 items (e, m-tile 128). Per stage: 2 TMA 64x64 tiles + 9216B bulk B.
__global__ __launch_bounds__(288, 2) void k_gemm1(const int* __restrict__ d_it, int it,
                                                  const float* __restrict__ ba,
                                                  const __grid_constant__ CUtensorMap tma_a) {
    if (it >= d_it[0]) return;
    extern __shared__ unsigned char dsm_raw[];
    __shared__ __align__(8) unsigned long long mbar_sto[2 * G1_NSTAGE];
    __shared__ int s_item;
    const uint32_t smem0 = ((uint32_t)__cvta_generic_to_shared(dsm_raw) + 1023u) & ~1023u;
    const uint32_t mb = (uint32_t)__cvta_generic_to_shared(mbar_sto);
    const int tid = threadIdx.x, w = tid >> 5, lane = tid & 31;

    if (tid == 0) {
        for (int s = 0; s < G1_NSTAGE; s++) {
            mbar_init(mb + s * 8, 1);                        // full: expect_tx arrival
            mbar_init(mb + (G1_NSTAGE + s) * 8, 8);          // empty: 8 consumer warps
        }
    }

    // consumer fragment addressing (item-invariant)
    const int m_idx = w >> 1;            // 0..3, warp covers m [m_idx*32, +32)
    const int n_base = (w & 1) * 32;
    const int g = lane >> 3, r = lane & 7;
    const int a_k = ((g >> 1) & 1) * 8 + r;
    uint32_t aoff[2];
#pragma unroll
    for (int j = 0; j < 2; j++)
        aoff[j] = (uint32_t)((a_k * 128 + ((m_idx & 1) * 32 + j * 16 + (g & 1) * 8) * 2) ^ (r << 4));
    const uint32_t a_qbase = (uint32_t)((m_idx >> 1) * 8192);
    const int b_k = (g & 1) * 8 + r;
    const int b_n = (g >> 1) * 8;
    const float inv = 1.0f / 4096.0f;
    __half2* actp = (__half2*)g_act16;

    // pipeline state persists across items
    int pst = 0, pph = 1;     // producer
    int cst = 0, cph = 0;     // consumer

    for (;;) {
        __syncthreads();
        if (tid == 0) s_item = atomicAdd(&g_ctr1[it], 1);
        __syncthreads();
        const int item = s_item;
        if (item >= G1_ITEMS) break;
        const int e = item / 32;
        const int m0 = (item & 31) * 128;

        if (w == 8) {
            if (lane == 0) {
                for (int kt = 0; kt < 64; kt++) {
                    const uint32_t fullb = mb + pst * 8;
                    const uint32_t emptyb = mb + (G1_NSTAGE + pst) * 8;
                    mbar_wait_rlx(emptyb, pph);
                    mbar_expect_tx(fullb, G1_STAGE);
                    const uint32_t sa = smem0 + pst * G1_STAGE;
                    tma3d(sa,        &tma_a, m0,      kt * 64, e, fullb);
                    tma3d(sa + 8192, &tma_a, m0 + 64, kt * 64, e, fullb);
                    bulkcp(sa + 16384, (const char*)g_h16p + (size_t)kt * 9216, 9216, fullb);
                    if (++pst == G1_NSTAGE) { pst = 0; pph ^= 1; }
                }
            }
            continue;
        }

        float acc[2][4][4];
#pragma unroll
        for (int j = 0; j < 2; j++)
#pragma unroll
            for (int t = 0; t < 4; t++) { acc[j][t][0] = acc[j][t][1] = acc[j][t][2] = acc[j][t][3] = 0.0f; }

        for (int kt = 0; kt < 64; kt++) {
            const uint32_t fullb = mb + cst * 8;
            const uint32_t emptyb = mb + (G1_NSTAGE + cst) * 8;
            mbar_wait_acq(fullb, cph);
            const uint32_t abase = smem0 + cst * G1_STAGE + a_qbase;
            const uint32_t bbase = smem0 + cst * G1_STAGE + 16384;
#pragma unroll
            for (int kk = 0; kk < 4; kk++) {
                unsigned a[4];
                ldsm4t_s(a[0], a[1], a[2], a[3], abase + aoff[0] + kk * 2048);
                unsigned b[8];
                const uint32_t brow = bbase + (kk * 16 + b_k) * 144;
                ldsm4t_s(b[0], b[1], b[2], b[3], brow + (n_base + b_n) * 2);
                ldsm4t_s(b[4], b[5], b[6], b[7], brow + (n_base + 16 + b_n) * 2);
                unsigned a2[4];
                ldsm4t_s(a2[0], a2[1], a2[2], a2[3], abase + aoff[1] + kk * 2048);
                mma16816(acc[0][0], a, b + 0);
                mma16816(acc[0][1], a, b + 2);
                mma16816(acc[0][2], a, b + 4);
                mma16816(acc[0][3], a, b + 6);
                mma16816(acc[1][0], a2, b + 0);
                mma16816(acc[1][1], a2, b + 2);
                mma16816(acc[1][2], a2, b + 4);
                mma16816(acc[1][3], a2, b + 6);
            }
            if (lane == 0) mbar_arrive(emptyb);
            if (++cst == G1_NSTAGE) { cst = 0; cph ^= 1; }
        }

        // epilogue
        const int cbase = n_base + 2 * (lane & 3);
#pragma unroll
        for (int j = 0; j < 2; j++) {
            const int rrow = m0 + m_idx * 32 + j * 16 + (lane >> 2);
#pragma unroll
            for (int t = 0; t < 4; t++) {
                int n = cbase + t * 8;
                float b0 = ba[n], b1 = ba[n + 1];
                __half2 v0 = __floats2half2_rn(acc[j][t][0] * inv + b0, acc[j][t][1] * inv + b1);
                __half2 v1 = __floats2half2_rn(acc[j][t][2] * inv + b0, acc[j][t][3] * inv + b1);
                size_t base0 = ((size_t)e * NN + rrow) * HH + n;
                actp[base0 >> 1] = v0;
                actp[(base0 + 8 * HH) >> 1] = v1;
            }
        }
    }
}

// ---------------- Update: S = sum_e act16[e]@W16[e] + h16@[uz|ur|0]; then gates ----------------
// m-tile 32 (grid 128), 8 warps x (16m x 48n), triple-buffered e-pipeline.
__global__ __launch_bounds__(256) void k_update(const int* __restrict__ d_it, int it,
                                                float* __restrict__ hio) {
    if (it >= d_it[0]) return;
    const int m0 = blockIdx.x * 32;
    extern __shared__ __align__(16) unsigned char upd[];

    const int tid = threadIdx.x, w = tid >> 5, lane = tid & 31;
    const int m_half = w & 1;            // 16 rows
    const int n_base = (w >> 1) * 48;    // 48 cols
    float acc[6][4];
#pragma unroll
    for (int t = 0; t < 6; t++) { acc[t][0] = acc[t][1] = acc[t][2] = acc[t][3] = 0.0f; }

    const int g = lane >> 3, r = lane & 7;
    const int a_row = m_half * 16 + (g & 1) * 8 + r;
    const int a_col = ((g >> 1) & 1) * 8;
    const int b_k = (g & 1) * 8 + r;
    const int b_nn = (g >> 1) * 8;

    auto load = [&](int e) {
        const int astride = (e < EE) ? 64 : 72;
        const __half* ag = (e < EE) ? g_act16 + ((size_t)e * NN + m0) * HH : g_h16p + (size_t)m0 * 72;
        const __half* bg = (e < EE) ? g_W16 + e * HH * NC : g_uzurpad16;
        unsigned char* buf = upd + (e % 3) * UP_BUF;
        __half (*As)[72]  = (__half(*)[72])buf;
        __half (*Bs)[200] = (__half(*)[200])(buf + UP_ABYTES);
        {   // A: 256 ops, 1 per thread
            int row = tid >> 3, ch = tid & 7;
            cp16(&As[row][ch * 8], ag + row * astride + ch * 8);
        }
        for (int c = tid; c < 1536; c += 256) {   // B: 6 per thread
            int row = c / 24, ch = c % 24;
            cp16(&Bs[row][ch * 8], bg + row * NC + ch * 8);
        }
        cp_commit();
    };

    load(0); load(1);
    for (int e = 0; e <= EE; e++) {
        if (e + 2 <= EE) { load(e + 2); cp_wait<2>(); }
        else if (e + 1 <= EE) { cp_wait<1>(); }
        else { cp_wait<0>(); }
        __syncthreads();
        const unsigned char* buf = upd + (e % 3) * UP_BUF;
        const __half (*As)[72]  = (const __half(*)[72])buf;
        const __half (*Bs)[200] = (const __half(*)[200])(buf + UP_ABYTES);
#pragma unroll
        for (int kk = 0; kk < 4; kk++) {
            unsigned a[4];
            ldsm4(a[0], a[1], a[2], a[3], &As[a_row][kk * 16 + a_col]);
#pragma unroll
            for (int p = 0; p < 3; p++) {
                unsigned b[4];
                ldsm4t(b[0], b[1], b[2], b[3], &Bs[kk * 16 + b_k][n_base + p * 16 + b_nn]);
                mma16816(acc[2 * p], a, b);
                mma16816(acc[2 * p + 1], a, b + 2);
            }
        }
        __syncthreads();
    }

    // write S tiles (fp32)
    {
        const int rrow = m0 + m_half * 16 + (lane >> 2);
        const int cb = n_base + 2 * (lane & 3);
        float2* sp = (float2*)g_S;
#pragma unroll
        for (int t = 0; t < 6; t++) {
            int n = cb + t * 8;
            sp[((size_t)rrow * NC + n) >> 1]       = make_float2(acc[t][0], acc[t][1]);
            sp[((size_t)(rrow + 8) * NC + n) >> 1] = make_float2(acc[t][2], acc[t][3]);
        }
    }
    __syncthreads();

    // ---- phase B: row-local gates (reuse smem) ----
    __half2* uh2 = (__half2*)upd;                      // 8192 B
    float (*rh_sm)[64] = (float(*)[64])(upd + 8192);   // 32*64*4 = 8192 B
    {
        const uint4* src = (const uint4*)g_uh16;
        uint4* dst = (uint4*)upd;
        for (int c = tid; c < 512; c += 256) dst[c] = src[c];
    }
    __syncthreads();

    const int c0 = 2 * lane;
    const int row0 = m0 + w * 4;       // each warp 4 rows
    float zz0[4], zz1[4], hv0[4], hv1[4];
#pragma unroll
    for (int q = 0; q < 4; q++) {
        int row = row0 + q;
        float2 s_z = *(const float2*)&g_S[(size_t)row * NC + c0];
        float2 t_z = *(const float2*)&g_T0[(size_t)row * NC + c0];
        float2 s_r = *(const float2*)&g_S[(size_t)row * NC + HH + c0];
        float2 t_r = *(const float2*)&g_T0[(size_t)row * NC + HH + c0];
        float2 h2  = *(const float2*)&hio[(size_t)row * HH + c0];
        float z0 = sigm(s_z.x + t_z.x), z1 = sigm(s_z.y + t_z.y);
        float r0v = sigm(s_r.x + t_r.x), r1v = sigm(s_r.y + t_r.y);
        zz0[q] = z0; zz1[q] = z1; hv0[q] = h2.x; hv1[q] = h2.y;
        rh_sm[w * 4 + q][c0] = r0v * h2.x;
        rh_sm[w * 4 + q][c0 + 1] = r1v * h2.y;
    }
    __syncwarp();

    float u0[4], u1[4];
#pragma unroll
    for (int q = 0; q < 4; q++) { u0[q] = 0.0f; u1[q] = 0.0f; }
#pragma unroll 4
    for (int i = 0; i < HH; i++) {
        float2 wv = __half22float2(uh2[i * 32 + lane]);
#pragma unroll
        for (int q = 0; q < 4; q++) {
            float rhv = rh_sm[w * 4 + q][i];
            u0[q] += rhv * wv.x;
            u1[q] += rhv * wv.y;
        }
    }

    __half2* h16pp = (__half2*)g_h16p;
#pragma unroll
    for (int q = 0; q < 4; q++) {
        int row = row0 + q;
        float2 s_h = *(const float2*)&g_S[(size_t)row * NC + 2 * HH + c0];
        float2 t_h = *(const float2*)&g_T0[(size_t)row * NC + 2 * HH + c0];
        float ht0 = tanh_fast(s_h.x + t_h.x + u0[q]);
        float ht1 = tanh_fast(s_h.y + t_h.y + u1[q]);
        float hn0 = hv0[q] + zz0[q] * (ht0 - hv0[q]);
        float hn1 = hv1[q] + zz1[q] * (ht1 - hv1[q]);
        *(float2*)&hio[(size_t)row * HH + c0] = make_float2(hn0, hn1);
        h16pp[((size_t)row * 72 + c0) >> 1] = __floats2half2_rn(hn0, hn1);
    }
}

// ---------------- launch ----------------
typedef CUresult (*EncodeFn)(CUtensorMap*, CUtensorMapDataType, cuuint32_t, void*,
                             const cuuint64_t*, const cuuint64_t*, const cuuint32_t*,
                             const cuuint32_t*, CUtensorMapInterleave, CUtensorMapSwizzle,
                             CUtensorMapL2promotion, CUtensorMapFloatOOBfill);

extern "C" void kernel_launch(void* const* d_in, const int* in_sizes, int n_in,
                              void* d_out, int out_size) {
    const float* input  = (const float*)d_in[0];
    const float* hidden = (const float*)d_in[1];
    const float* edge   = (const float*)d_in[2];
    const float* ba     = (const float*)d_in[3];
    const float* W      = (const float*)d_in[4];
    const float* uzur   = (const float*)d_in[5];
    const float* uh     = (const float*)d_in[6];
    const float* iwzrh  = (const float*)d_in[7];
    const int*   d_it   = (const int*)d_in[8];
    float* out = (float*)d_out;

    cudaFuncSetAttribute(k_gemm1, cudaFuncAttributeMaxDynamicSharedMemorySize, G1_SMEM);
    cudaFuncSetAttribute(k_update, cudaFuncAttributeMaxDynamicSharedMemorySize, UP_SMEM);

    // Tensormap for g_edge16 viewed as 3D [m=4096, k=4096, e=10], SW128, box 64x64x1
    CUtensorMap tma_a;
    {
        void* edge16_dev = nullptr;
        cudaGetSymbolAddress(&edge16_dev, g_edge16);
        EncodeFn enc = nullptr;
#if CUDART_VERSION >= 12000
        cudaDriverEntryPointQueryResult qres;
        cudaGetDriverEntryPoint("cuTensorMapEncodeTiled", (void**)&enc, cudaEnableDefault, &qres);
#else
        cudaGetDriverEntryPoint("cuTensorMapEncodeTiled", (void**)&enc, cudaEnableDefault);
#endif
        cuuint64_t dims[3]    = {NN, NN, EE};
        cuuint64_t strides[2] = {(cuuint64_t)NN * 2, (cuuint64_t)NN * NN * 2};
        cuuint32_t box[3]     = {64, 64, 1};
        cuuint32_t es[3]      = {1, 1, 1};
        if (enc) {
            enc(&tma_a, CU_TENSOR_MAP_DATA_TYPE_FLOAT16, 3, edge16_dev,
                dims, strides, box, es,
                CU_TENSOR_MAP_INTERLEAVE_NONE, CU_TENSOR_MAP_SWIZZLE_128B,
                CU_TENSOR_MAP_L2_PROMOTION_L2_128B, CU_TENSOR_MAP_FLOAT_OOB_FILL_NONE);
        }
    }

    k_conv_edge<<<8192, 256>>>(edge);
    k_setup<<<(NN * HH + 255) / 256, 256>>>(hidden, W, uzur, uh, out);
    k_t0<<<NN, NC>>>(input, iwzrh);

    for (int it = 0; it < 10; ++it) {
        k_gemm1<<<G1_GRID, 288, G1_SMEM>>>(d_it, it, ba, tma_a);
        k_update<<<NN / 32, 256, UP_SMEM>>>(d_it, it, out);
    }
}